// round 5
// baseline (speedup 1.0000x reference)
#include <cuda_runtime.h>
#include <cuda_bf16.h>

// LSTMHierarchialAttention2 — constant-folded output. FINAL (converged).
//
// Reference ends with softmax over a singleton axis:
//     logits = doc @ Wf.T + bf            # shape (1, 1)
//     return jax.nn.softmax(logits, axis=1)   # == 1.0f exactly
//
// e^x / e^x == 1.0f for any finite fp32 x, so both LSTM scans (8192
// sequential word steps + 32 sentence steps), both attention reductions,
// and the final linear are dead code w.r.t. the output. The bit-exact
// correct result is the constant 1.0f, independent of all inputs.
//
// Floor-probe history (graph-replay dur_us, timer tick = 0.256 us):
//   R1  <<<1,32>>> + bounds check : 4.86
//   R2  <<<1,1>>>  single STG     : 4.61  <- floor
//   R3  4B D2D memcpy graph node  : 4.86  (memcpy node NOT cheaper)
//   R4  R2 re-bench               : 4.61  (reproduced; ncu dur 3.296 us)
// ncu: all pipes 0.0%, kernel dur invariant to body — pure single-node
// graph dispatch overhead. The minimum graph for a constant function is
// one 4-byte-store node; both available node types probed; kernel node
// wins. Converged.

__global__ void __launch_bounds__(1) write_one_kernel(float* __restrict__ out) {
    *out = 1.0f;
}

__global__ void write_one_n_kernel(float* __restrict__ out, int n) {
    int i = blockIdx.x * blockDim.x + threadIdx.x;
    if (i < n) out[i] = 1.0f;
}

extern "C" void kernel_launch(void* const* d_in, const int* in_sizes, int n_in,
                              void* d_out, int out_size) {
    (void)d_in; (void)in_sizes; (void)n_in;
    float* out = (float*)d_out;
    if (out_size == 1) {
        // Actual case: output shape (1,1) fp32 — one unconditional store.
        write_one_kernel<<<1, 1>>>(out);
    } else {
        // Safety net for padded out_size.
        int threads = 128;
        int blocks = (out_size + threads - 1) / threads;
        write_one_n_kernel<<<blocks, threads>>>(out, out_size);
    }
}

// round 6
// speedup vs baseline: 1.0596x; 1.0596x over previous
#include <cuda_runtime.h>
#include <cuda_bf16.h>

// LSTMHierarchialAttention2 — constant-folded output. FINAL (converged).
//
// Reference ends with softmax over a singleton axis:
//     logits = doc @ Wf.T + bf            # shape (1, 1)
//     return jax.nn.softmax(logits, axis=1)   # == 1.0f exactly
//
// e^x / e^x == 1.0f for any finite fp32 x, so both LSTM scans (8192
// sequential word steps + 32 sentence steps), both attention reductions,
// and the final linear are dead code w.r.t. the output. The bit-exact
// correct result is the constant 1.0f, independent of all inputs.
//
// Floor-probe + noise-calibration history (timer tick = 0.256 us):
//   R1  <<<1,32>>> + bounds check : 4.86
//   R2  <<<1,1>>>  single STG     : 4.61
//   R3  4B D2D memcpy graph node  : 4.86  (memcpy node NOT cheaper)
//   R4  R2 re-bench               : 4.61  (ncu dur 3.296 us)
//   R5  R4 identical source       : 5.12  (ncu dur 3.328 us)
// => harness graph-replay noise is +/- 2 ticks (~0.5 us) for IDENTICAL
//    code; ncu kernel dur stable at ~3.3 us and invariant to body.
//    Remaining headroom < noise. Minimum graph for a constant function is
//    one 4-byte-store node; kernel node is the cheapest node type probed.
//    Converged at best-measured 4.608 us.

__global__ void __launch_bounds__(1) write_one_kernel(float* __restrict__ out) {
    *out = 1.0f;
}

__global__ void write_one_n_kernel(float* __restrict__ out, int n) {
    int i = blockIdx.x * blockDim.x + threadIdx.x;
    if (i < n) out[i] = 1.0f;
}

extern "C" void kernel_launch(void* const* d_in, const int* in_sizes, int n_in,
                              void* d_out, int out_size) {
    (void)d_in; (void)in_sizes; (void)n_in;
    float* out = (float*)d_out;
    if (out_size == 1) {
        // Actual case: output shape (1,1) fp32 — one unconditional store.
        write_one_kernel<<<1, 1>>>(out);
    } else {
        // Safety net for padded out_size.
        int threads = 128;
        int blocks = (out_size + threads - 1) / threads;
        write_one_n_kernel<<<blocks, threads>>>(out, out_size);
    }
}